// round 14
// baseline (speedup 1.0000x reference)
#include <cuda_runtime.h>
#include <cuda_fp16.h>
#include <math.h>

#define BATCH 32
#define H 512
#define W 512
#define HW (H*W)
#define NTOT (BATCH*HW)
#define KK_INV (1.0f/961.0f)

#define ROWS_PB 16
#define NSLOT 36
#define NTHR 128
#define NBLKY (H / ROWS_PB)                 // 32
#define NBLK (BATCH * NBLKY)                // 1024
#define CHUNKS_PER_IMG NBLKY                // 32

#define CB_BYTES   (NSLOT * W * 2)          // 36864
#define SMEM_TOTAL CB_BYTES                 // red aliases the dead ring

__device__ float g_part[NBLK][4];           // {bce, wsum, inter, union}
__device__ unsigned g_done = 0;

__device__ __forceinline__ int slotof(int row) {
    return (unsigned)(row + 72) % NSLOT;    // row >= -15 always
}

// Emit output chunk m (32 quads): out[x] = P[x+15] - P[x-16], using prefix
// quads of chunks m-1 (Qp), m (Qc), m+1 (Qn). 16 shuffles per 128 elems.
__device__ __forceinline__ void emit_chunk(uint2* __restrict__ cb2, int m,
                                           float4 Qp, float4 Qc, float4 Qn,
                                           int lane) {
    const unsigned FULL = 0xffffffffu;
    const int lp3 = (lane + 3) & 31;
    const int lp4 = (lane + 4) & 31;
    const int lm4 = (lane - 4) & 31;

    float axm = __shfl_sync(FULL, Qc.w, lp3), axn = __shfl_sync(FULL, Qn.w, lp3);
    float aym = __shfl_sync(FULL, Qc.x, lp4), ayn = __shfl_sync(FULL, Qn.x, lp4);
    float azm = __shfl_sync(FULL, Qc.y, lp4), azn = __shfl_sync(FULL, Qn.y, lp4);
    float awm = __shfl_sync(FULL, Qc.z, lp4), awn = __shfl_sync(FULL, Qn.z, lp4);
    float Ax = (lane <= 28) ? axm : axn;
    float Ay = (lane <= 27) ? aym : ayn;
    float Az = (lane <= 27) ? azm : azn;
    float Aw = (lane <= 27) ? awm : awn;

    float bxm = __shfl_sync(FULL, Qc.x, lm4), bxp = __shfl_sync(FULL, Qp.x, lm4);
    float bym = __shfl_sync(FULL, Qc.y, lm4), byp = __shfl_sync(FULL, Qp.y, lm4);
    float bzm = __shfl_sync(FULL, Qc.z, lm4), bzp = __shfl_sync(FULL, Qp.z, lm4);
    float bwm = __shfl_sync(FULL, Qc.w, lm4), bwp = __shfl_sync(FULL, Qp.w, lm4);
    float Bx = (lane >= 4) ? bxm : bxp;
    float By = (lane >= 4) ? bym : byp;
    float Bz = (lane >= 4) ? bzm : bzp;
    float Bw = (lane >= 4) ? bwm : bwp;

    __half2 h0 = __floats2half2_rn(Ax - Bx, Ay - By);
    __half2 h1 = __floats2half2_rn(Az - Bz, Aw - Bw);
    uint2 u;
    u.x = *reinterpret_cast<unsigned*>(&h0);
    u.y = *reinterpret_cast<unsigned*>(&h1);
    cb2[m * 32 + lane] = u;
}

// Warp computes the 31-wide horizontal box sum of one full targ row into an
// fp16 ring row. Pure-register quad pipeline; no smem scratch.
__device__ __forceinline__ void produce_row(const float* __restrict__ tb, int row,
                                            __half* __restrict__ cbrow, int lane) {
    uint2* cb2 = (uint2*)cbrow;
    if (row < 0 || row >= H) {
        #pragma unroll
        for (int c = 0; c < 4; ++c) cb2[c * 32 + lane] = make_uint2(0u, 0u);
        return;
    }
    const unsigned FULL = 0xffffffffu;
    const float4* __restrict__ rowp = (const float4*)(tb + (size_t)row * W);

    float carry = 0.0f;
    float4 Qa = make_float4(0.f, 0.f, 0.f, 0.f);
    float4 Qb = make_float4(0.f, 0.f, 0.f, 0.f);

    #pragma unroll
    for (int c = 0; c < 4; ++c) {
        float4 q = rowp[c * 32 + lane];
        float p0 = q.x;
        float p1 = p0 + q.y;
        float p2 = p1 + q.z;
        float p3 = p2 + q.w;
        float s = p3;
        #pragma unroll
        for (int off = 1; off < 32; off <<= 1) {
            float n = __shfl_up_sync(FULL, s, off);
            if (lane >= off) s += n;
        }
        const float base = s - p3 + carry;
        float4 Qc = make_float4(base + p0, base + p1, base + p2, base + p3);
        carry += __shfl_sync(FULL, s, 31);

        if (c >= 1) emit_chunk(cb2, c - 1, Qa, Qb, Qc, lane);
        Qa = Qb;
        Qb = Qc;
    }
    float4 Qt = make_float4(carry, carry, carry, carry);
    emit_chunk(cb2, 3, Qa, Qb, Qt, lane);
}

__device__ __forceinline__ void lane_math(float xv, float tv, float vsum,
                                          float& bce, float& ws, float& it, float& un) {
    const float w   = fmaf(5.0f, fabsf(vsum * KK_INV - tv), 1.0f);
    const float E   = __expf(-fabsf(xv));
    const float u   = 1.0f + E;
    const float sp  = fmaxf(xv, 0.0f) + __logf(u);
    const float inv = __fdividef(1.0f, u);
    const float p   = (xv >= 0.0f) ? inv : E * inv;
    bce += sp - xv * tv;
    ws  += w;
    it  += p * tv * w;
    un  += (p + tv) * w;
}

// ---------------------------------------------------------------------------
// Fused kernel: grid (32, 32) = 1024 blocks, block 128 (4 warps), 16-row tiles.
// Groups of 4 rows: 4 warps produce 4 fp16 ring rows, then 128 threads
// (4 cols each) consume. Last finished block performs the global finalize.
// ---------------------------------------------------------------------------
extern __shared__ char smem_raw[];

__global__ __launch_bounds__(NTHR, 6)
void fused_kernel(const float* __restrict__ pred,
                  const float* __restrict__ targ,
                  float* __restrict__ out) {
    __half* CB = (__half*)smem_raw;                  // [NSLOT][W]

    const int b    = blockIdx.y;
    const int tid  = threadIdx.x;
    const int w    = tid >> 5;
    const int lane = tid & 31;
    const int r0   = blockIdx.x * ROWS_PB;

    const float* __restrict__ tb = targ + (size_t)b * HW;
    const float* __restrict__ pb = pred + (size_t)b * HW;
    const float4* __restrict__ tb4 = (const float4*)tb;
    const float4* __restrict__ pb4 = (const float4*)pb;

    // Prologue: ring rows r0-15 .. r0+15 (31 rows, 4 warps, 8 rounds)
    #pragma unroll
    for (int k = 0; k < 8; ++k) {
        const int i = k * 4 + w;
        if (i < 31) {
            const int row = r0 - 15 + i;
            produce_row(tb, row, CB + slotof(row) * W, lane);
        }
    }
    __syncthreads();

    // Initial vertical window (4 cols per thread)
    float vx = 0.f, vy = 0.f, vz = 0.f, vw = 0.f;
    #pragma unroll
    for (int i = 0; i < 31; ++i) {
        const int row = r0 - 15 + i;
        uint2 u = ((const uint2*)(CB + slotof(row) * W))[tid];
        float2 a = __half22float2(*reinterpret_cast<__half2*>(&u.x));
        float2 c = __half22float2(*reinterpret_cast<__half2*>(&u.y));
        vx += a.x; vy += a.y; vz += c.x; vw += c.y;
    }

    float bce_a = 0.f, wsum_a = 0.f, inter_a = 0.f, uni_a = 0.f;

    #pragma unroll
    for (int gr = 0; gr < ROWS_PB / 4; ++gr) {
        const int r = r0 + gr * 4;
        // Produce rows r+16 .. r+19, one per warp
        {
            const int row = r + 16 + w;
            produce_row(tb, row, CB + slotof(row) * W, lane);
        }
        __syncthreads();

        #pragma unroll
        for (int j = 0; j < 4; ++j) {
            const int rr = r + j;
            const float4 tv = tb4[rr * (W/4) + tid];
            const float4 xv = pb4[rr * (W/4) + tid];

            lane_math(xv.x, tv.x, vx, bce_a, wsum_a, inter_a, uni_a);
            lane_math(xv.y, tv.y, vy, bce_a, wsum_a, inter_a, uni_a);
            lane_math(xv.z, tv.z, vz, bce_a, wsum_a, inter_a, uni_a);
            lane_math(xv.w, tv.w, vw, bce_a, wsum_a, inter_a, uni_a);

            // slide: add row rr+16, subtract row rr-15
            uint2 ua = ((const uint2*)(CB + slotof(rr + 16) * W))[tid];
            uint2 us = ((const uint2*)(CB + slotof(rr - 15) * W))[tid];
            float2 aa = __half22float2(*reinterpret_cast<__half2*>(&ua.x));
            float2 ab = __half22float2(*reinterpret_cast<__half2*>(&ua.y));
            float2 sa = __half22float2(*reinterpret_cast<__half2*>(&us.x));
            float2 sb = __half22float2(*reinterpret_cast<__half2*>(&us.y));
            vx += aa.x - sa.x;
            vy += aa.y - sa.y;
            vz += ab.x - sb.x;
            vw += ab.y - sb.y;
        }
        __syncthreads();   // ring slots free before next produce
    }

    // Reduction scratch aliases the now-dead ring.
    float* red = (float*)smem_raw;   // [4][NTHR]
    red[0 * NTHR + tid] = bce_a;
    red[1 * NTHR + tid] = wsum_a;
    red[2 * NTHR + tid] = inter_a;
    red[3 * NTHR + tid] = uni_a;
    __syncthreads();
    #pragma unroll
    for (int off = NTHR / 2; off > 0; off >>= 1) {
        if (tid < off) {
            red[0 * NTHR + tid] += red[0 * NTHR + tid + off];
            red[1 * NTHR + tid] += red[1 * NTHR + tid + off];
            red[2 * NTHR + tid] += red[2 * NTHR + tid + off];
            red[3 * NTHR + tid] += red[3 * NTHR + tid + off];
        }
        __syncthreads();
    }

    __shared__ unsigned last_flag;
    if (tid == 0) {
        const int blin = b * CHUNKS_PER_IMG + blockIdx.x;
        g_part[blin][0] = red[0 * NTHR];
        g_part[blin][1] = red[1 * NTHR];
        g_part[blin][2] = red[2 * NTHR];
        g_part[blin][3] = red[3 * NTHR];
        __threadfence();
        last_flag = (atomicAdd(&g_done, 1u) == NBLK - 1u);
    }
    __syncthreads();
    if (!last_flag) return;

    // ---- Last block: global finalize (fixed-order sums) ----
    __threadfence();
    if (tid == 0) g_done = 0;    // reset for next graph replay

    float acc = 0.0f;
    #pragma unroll
    for (int j = 0; j < NBLK / NTHR; ++j) acc += g_part[tid * (NBLK / NTHR) + j][0];
    red[tid] = acc;
    __syncthreads();
    #pragma unroll
    for (int off = NTHR / 2; off > 0; off >>= 1) {
        if (tid < off) red[tid] += red[tid + off];
        __syncthreads();
    }
    const float bce = red[0] * (1.0f / (float)NTOT);
    __syncthreads();

    if (tid < BATCH) {
        float ws = 0.0f, it = 0.0f, un = 0.0f;
        #pragma unroll
        for (int j = 0; j < CHUNKS_PER_IMG; ++j) {
            const int bl = tid * CHUNKS_PER_IMG + j;
            ws += g_part[bl][1];
            it += g_part[bl][2];
            un += g_part[bl][3];
        }
        const float w_bce = (ws * bce + 1e-8f) / (ws + 1e-8f);
        const float w_iou = 1.0f - (it + 1.0f + 1e-8f) / (un - it + 1.0f + 1e-8f);
        red[NTHR + tid] = w_bce + w_iou;   // separate region, still in dead ring
    }
    __syncthreads();
    if (tid == 0) {
        float a = 0.0f;
        #pragma unroll
        for (int i = 0; i < BATCH; ++i) a += red[NTHR + i];
        out[0] = a * (1.0f / (float)BATCH);
    }
}

// ---------------------------------------------------------------------------
extern "C" void kernel_launch(void* const* d_in, const int* in_sizes, int n_in,
                              void* d_out, int out_size) {
    const float* y_pred   = (const float*)d_in[0];
    const float* y_target = (const float*)d_in[1];
    float* out = (float*)d_out;

    dim3 g(NBLKY, BATCH);             // (32, 32) = 1024 blocks
    fused_kernel<<<g, NTHR, SMEM_TOTAL>>>(y_pred, y_target, out);
}

// round 15
// speedup vs baseline: 1.5271x; 1.5271x over previous
#include <cuda_runtime.h>
#include <cuda_fp16.h>
#include <math.h>

#define BATCH 32
#define H 512
#define W 512
#define HW (H*W)
#define NTOT (BATCH*HW)
#define KK_INV (1.0f/961.0f)

#define ROWS_PB 32
#define NSLOT 36
#define NTHR 128
#define NBLKY (H / ROWS_PB)                 // 16
#define NBLK (BATCH * NBLKY)                // 512
#define CHUNKS_PER_IMG NBLKY                // 16

#define CB_BYTES   (NSLOT * W * 2)          // 36864
#define PSCR_BYTES (4 * W * 4)              // 8192
#define RED_BYTES  (4 * NTHR * 4)           // 2048
#define SMEM_TOTAL (CB_BYTES + PSCR_BYTES + RED_BYTES)   // 47104

__device__ float g_part[NBLK][4];           // {bce, wsum, inter, union}
__device__ unsigned g_done = 0;

__device__ __forceinline__ int slotof(int row) {
    return (unsigned)(row + 72) % NSLOT;    // row >= -15 always
}

__device__ __forceinline__ float tanh_fast(float x) {
    float r;
    asm("tanh.approx.f32 %0, %1;" : "=f"(r) : "f"(x));
    return r;
}

// ---------------------------------------------------------------------------
// Warp computes the 31-wide horizontal box sum of one targ row into an fp16
// ring row. Chain-broken: all 4 chunks loaded up front, 4 warp scans run in
// parallel (4-way ILP), carries combined afterwards. Gather via Pscr smem.
// ---------------------------------------------------------------------------
__device__ __forceinline__ void compute_hsum_row(
    const float* __restrict__ tb, int row, float* Pw, __half* cbrow, int lane) {
    uint2* cb2 = (uint2*)cbrow;
    if (row < 0 || row >= H) {
        #pragma unroll
        for (int c = 0; c < 4; ++c) cb2[c * 32 + lane] = make_uint2(0u, 0u);
        return;
    }
    const unsigned FULL = 0xffffffffu;
    const float4* __restrict__ rowp = (const float4*)(tb + (size_t)row * W);
    float4* P4 = (float4*)Pw;

    // Front-batched loads (MLP = 4)
    const float4 q0 = rowp[lane];
    const float4 q1 = rowp[32 + lane];
    const float4 q2 = rowp[64 + lane];
    const float4 q3 = rowp[96 + lane];

    // Intra-quad inclusive prefixes
    const float a1 = q0.x, a2 = a1 + q0.y, a3 = a2 + q0.z, a4 = a3 + q0.w;
    const float b1 = q1.x, b2 = b1 + q1.y, b3 = b2 + q1.z, b4 = b3 + q1.w;
    const float c1 = q2.x, c2 = c1 + q2.y, c3 = c2 + q2.z, c4 = c3 + q2.w;
    const float d1 = q3.x, d2 = d1 + q3.y, d3 = d2 + q3.z, d4 = d3 + q3.w;

    // Four parallel warp scans of quad totals
    float s0 = a4, s1 = b4, s2 = c4, s3 = d4;
    #pragma unroll
    for (int off = 1; off < 32; off <<= 1) {
        float n0 = __shfl_up_sync(FULL, s0, off);
        float n1 = __shfl_up_sync(FULL, s1, off);
        float n2 = __shfl_up_sync(FULL, s2, off);
        float n3 = __shfl_up_sync(FULL, s3, off);
        if (lane >= off) { s0 += n0; s1 += n1; s2 += n2; s3 += n3; }
    }
    const float T0 = __shfl_sync(FULL, s0, 31);
    const float T1 = __shfl_sync(FULL, s1, 31);
    const float T2 = __shfl_sync(FULL, s2, 31);
    const float T3 = __shfl_sync(FULL, s3, 31);

    const float e0 = s0 - a4;                  // exclusive bases
    const float e1 = T0 + (s1 - b4);
    const float e2 = T0 + T1 + (s2 - c4);
    const float e3 = T0 + T1 + T2 + (s3 - d4);
    const float total = T0 + T1 + T2 + T3;

    P4[lane]      = make_float4(e0 + a1, e0 + a2, e0 + a3, e0 + a4);
    P4[32 + lane] = make_float4(e1 + b1, e1 + b2, e1 + b3, e1 + b4);
    P4[64 + lane] = make_float4(e2 + c1, e2 + c2, e2 + c3, e2 + c4);
    P4[96 + lane] = make_float4(e3 + d1, e3 + d2, e3 + d3, e3 + d4);
    __syncwarp();

    // out[x] = P[min(x+15,511)] - (x>=16 ? P[x-16] : 0)
    #pragma unroll
    for (int c = 0; c < 4; ++c) {
        const int g = c * 32 + lane;
        float4 A;
        if (g < 124) {
            float4 Q1 = P4[g + 3];
            float4 Q2 = P4[g + 4];
            A = make_float4(Q1.w, Q2.x, Q2.y, Q2.z);
        } else {
            A = make_float4(total, total, total, total);
        }
        float4 B = (g >= 4) ? P4[g - 4] : make_float4(0.f, 0.f, 0.f, 0.f);
        __half2 h0 = __floats2half2_rn(A.x - B.x, A.y - B.y);
        __half2 h1 = __floats2half2_rn(A.z - B.z, A.w - B.w);
        uint2 u;
        u.x = *reinterpret_cast<unsigned*>(&h0);
        u.y = *reinterpret_cast<unsigned*>(&h1);
        cb2[g] = u;
    }
}

// 2-MUFU loss math: p via tanh.approx, softplus via log of the same tanh.
__device__ __forceinline__ void lane_math(float xv, float tv, float vsum,
                                          float& bce, float& ws, float& it, float& un) {
    const float w  = fmaf(5.0f, fabsf(vsum * KK_INV - tv), 1.0f);
    const float th = tanh_fast(0.5f * xv);
    const float p  = fmaf(0.5f, th, 0.5f);
    const float sp = fmaxf(xv, 0.0f) - __logf(fmaf(0.5f, fabsf(th), 0.5f));
    bce += sp - xv * tv;
    ws  += w;
    it  += p * tv * w;
    un  += (p + tv) * w;
}

// ---------------------------------------------------------------------------
// Fused kernel: grid (16, 32) = 512 blocks, block 128 (4 warps).
// 4-row groups: prefetch tv/xv -> produce 4 ring rows -> consume 4 rows.
// Last finished block performs the global finalize.
// ---------------------------------------------------------------------------
extern __shared__ char smem_raw[];

__global__ __launch_bounds__(NTHR, 4)
void fused_kernel(const float* __restrict__ pred,
                  const float* __restrict__ targ,
                  float* __restrict__ out) {
    __half* CB   = (__half*)smem_raw;                            // [NSLOT][W]
    float*  Pscr = (float*)(smem_raw + CB_BYTES);                // [4][W]
    float*  red  = (float*)(smem_raw + CB_BYTES + PSCR_BYTES);   // [4][NTHR]

    const int b    = blockIdx.y;
    const int tid  = threadIdx.x;
    const int w    = tid >> 5;
    const int lane = tid & 31;
    const int r0   = blockIdx.x * ROWS_PB;

    const float* __restrict__ tb = targ + (size_t)b * HW;
    const float* __restrict__ pb = pred + (size_t)b * HW;
    const float4* __restrict__ tb4 = (const float4*)tb;
    const float4* __restrict__ pb4 = (const float4*)pb;

    // Prologue: ring rows r0-15 .. r0+15 (31 rows, 4 warps, 8 rounds)
    #pragma unroll
    for (int k = 0; k < 8; ++k) {
        const int i = k * 4 + w;
        if (i < 31) {
            const int row = r0 - 15 + i;
            compute_hsum_row(tb, row, Pscr + w * W, CB + slotof(row) * W, lane);
        }
    }
    __syncthreads();

    // Initial vertical window (4 cols per thread)
    float vx = 0.f, vy = 0.f, vz = 0.f, vw = 0.f;
    #pragma unroll
    for (int i = 0; i < 31; ++i) {
        const int row = r0 - 15 + i;
        uint2 u = ((const uint2*)(CB + slotof(row) * W))[tid];
        float2 a = __half22float2(*reinterpret_cast<__half2*>(&u.x));
        float2 c = __half22float2(*reinterpret_cast<__half2*>(&u.y));
        vx += a.x; vy += a.y; vz += c.x; vw += c.y;
    }

    float bce_a = 0.f, wsum_a = 0.f, inter_a = 0.f, uni_a = 0.f;

    #pragma unroll
    for (int gr = 0; gr < ROWS_PB / 4; ++gr) {
        const int r = r0 + gr * 4;

        // Prefetch this group's tv/xv (gmem, independent of ring state):
        // produce_row's long scan hides the load latency.
        float4 TV[4], XV[4];
        #pragma unroll
        for (int j = 0; j < 4; ++j) {
            TV[j] = tb4[(r + j) * (W/4) + tid];
            XV[j] = pb4[(r + j) * (W/4) + tid];
        }

        // Produce rows r+16 .. r+19, one per warp
        {
            const int row = r + 16 + w;
            compute_hsum_row(tb, row, Pscr + w * W, CB + slotof(row) * W, lane);
        }
        __syncthreads();

        #pragma unroll
        for (int j = 0; j < 4; ++j) {
            const int rr = r + j;
            lane_math(XV[j].x, TV[j].x, vx, bce_a, wsum_a, inter_a, uni_a);
            lane_math(XV[j].y, TV[j].y, vy, bce_a, wsum_a, inter_a, uni_a);
            lane_math(XV[j].z, TV[j].z, vz, bce_a, wsum_a, inter_a, uni_a);
            lane_math(XV[j].w, TV[j].w, vw, bce_a, wsum_a, inter_a, uni_a);

            // slide: add row rr+16, subtract row rr-15
            uint2 ua = ((const uint2*)(CB + slotof(rr + 16) * W))[tid];
            uint2 us = ((const uint2*)(CB + slotof(rr - 15) * W))[tid];
            float2 aa = __half22float2(*reinterpret_cast<__half2*>(&ua.x));
            float2 ab = __half22float2(*reinterpret_cast<__half2*>(&ua.y));
            float2 sa = __half22float2(*reinterpret_cast<__half2*>(&us.x));
            float2 sb = __half22float2(*reinterpret_cast<__half2*>(&us.y));
            vx += aa.x - sa.x;
            vy += aa.y - sa.y;
            vz += ab.x - sb.x;
            vw += ab.y - sb.y;
        }
        __syncthreads();   // ring slots free before next produce
    }

    // Deterministic block reduction (fixed order)
    red[0 * NTHR + tid] = bce_a;
    red[1 * NTHR + tid] = wsum_a;
    red[2 * NTHR + tid] = inter_a;
    red[3 * NTHR + tid] = uni_a;
    __syncthreads();
    #pragma unroll
    for (int off = NTHR / 2; off > 0; off >>= 1) {
        if (tid < off) {
            red[0 * NTHR + tid] += red[0 * NTHR + tid + off];
            red[1 * NTHR + tid] += red[1 * NTHR + tid + off];
            red[2 * NTHR + tid] += red[2 * NTHR + tid + off];
            red[3 * NTHR + tid] += red[3 * NTHR + tid + off];
        }
        __syncthreads();
    }

    __shared__ unsigned last_flag;
    if (tid == 0) {
        const int blin = b * CHUNKS_PER_IMG + blockIdx.x;
        g_part[blin][0] = red[0 * NTHR];
        g_part[blin][1] = red[1 * NTHR];
        g_part[blin][2] = red[2 * NTHR];
        g_part[blin][3] = red[3 * NTHR];
        __threadfence();
        last_flag = (atomicAdd(&g_done, 1u) == NBLK - 1u);
    }
    __syncthreads();
    if (!last_flag) return;

    // ---- Last block: global finalize (fixed-order sums) ----
    __threadfence();
    if (tid == 0) g_done = 0;    // reset for next graph replay

    float acc = 0.0f;
    #pragma unroll
    for (int j = 0; j < NBLK / NTHR; ++j) acc += g_part[tid * (NBLK / NTHR) + j][0];
    red[tid] = acc;
    __syncthreads();
    #pragma unroll
    for (int off = NTHR / 2; off > 0; off >>= 1) {
        if (tid < off) red[tid] += red[tid + off];
        __syncthreads();
    }
    const float bce = red[0] * (1.0f / (float)NTOT);
    __syncthreads();

    if (tid < BATCH) {
        float ws = 0.0f, it = 0.0f, un = 0.0f;
        #pragma unroll
        for (int j = 0; j < CHUNKS_PER_IMG; ++j) {
            const int bl = tid * CHUNKS_PER_IMG + j;
            ws += g_part[bl][1];
            it += g_part[bl][2];
            un += g_part[bl][3];
        }
        const float w_bce = (ws * bce + 1e-8f) / (ws + 1e-8f);
        const float w_iou = 1.0f - (it + 1.0f + 1e-8f) / (un - it + 1.0f + 1e-8f);
        red[NTHR + tid] = w_bce + w_iou;
    }
    __syncthreads();
    if (tid == 0) {
        float a = 0.0f;
        #pragma unroll
        for (int i = 0; i < BATCH; ++i) a += red[NTHR + i];
        out[0] = a * (1.0f / (float)BATCH);
    }
}

// ---------------------------------------------------------------------------
extern "C" void kernel_launch(void* const* d_in, const int* in_sizes, int n_in,
                              void* d_out, int out_size) {
    const float* y_pred   = (const float*)d_in[0];
    const float* y_target = (const float*)d_in[1];
    float* out = (float*)d_out;

    cudaFuncSetAttribute(fused_kernel, cudaFuncAttributeMaxDynamicSharedMemorySize,
                         SMEM_TOTAL);

    dim3 g(NBLKY, BATCH);             // (16, 32) = 512 blocks
    fused_kernel<<<g, NTHR, SMEM_TOTAL>>>(y_pred, y_target, out);
}

// round 16
// speedup vs baseline: 1.5897x; 1.0410x over previous
#include <cuda_runtime.h>
#include <cuda_fp16.h>
#include <math.h>

#define BATCH 32
#define H 512
#define W 512
#define HW (H*W)
#define NTOT (BATCH*HW)
#define KK_INV (1.0f/961.0f)

#define ROWS_PB 32
#define NSLOT 44
#define NTHR 128
#define NBLKY (H / ROWS_PB)                 // 16
#define NBLK (BATCH * NBLKY)                // 512
#define CHUNKS_PER_IMG NBLKY                // 16

#define CB_BYTES   (NSLOT * W * 2)          // 45056
#define PSCR_BYTES (4 * W * 4)              // 8192
#define RED_BYTES  (4 * NTHR * 4)           // 2048
#define SMEM_TOTAL (CB_BYTES + PSCR_BYTES + RED_BYTES)   // 55296

__device__ float g_part[NBLK][4];           // {bce, wsum, inter, union}
__device__ unsigned g_done = 0;

__device__ __forceinline__ int slotof(int row) {
    return (unsigned)(row + 88) % NSLOT;    // row >= -15 always
}

__device__ __forceinline__ float tanh_fast(float x) {
    float r;
    asm("tanh.approx.f32 %0, %1;" : "=f"(r) : "f"(x));
    return r;
}

// ---------------------------------------------------------------------------
// Warp computes the 31-wide horizontal box sum of one targ row into an fp16
// ring row. Chain-broken: 4 front-batched loads, 4 warp scans in parallel.
// ---------------------------------------------------------------------------
__device__ __forceinline__ void compute_hsum_row(
    const float* __restrict__ tb, int row, float* Pw, __half* cbrow, int lane) {
    uint2* cb2 = (uint2*)cbrow;
    if (row < 0 || row >= H) {
        #pragma unroll
        for (int c = 0; c < 4; ++c) cb2[c * 32 + lane] = make_uint2(0u, 0u);
        return;
    }
    const unsigned FULL = 0xffffffffu;
    const float4* __restrict__ rowp = (const float4*)(tb + (size_t)row * W);
    float4* P4 = (float4*)Pw;

    const float4 q0 = rowp[lane];
    const float4 q1 = rowp[32 + lane];
    const float4 q2 = rowp[64 + lane];
    const float4 q3 = rowp[96 + lane];

    const float a1 = q0.x, a2 = a1 + q0.y, a3 = a2 + q0.z, a4 = a3 + q0.w;
    const float b1 = q1.x, b2 = b1 + q1.y, b3 = b2 + q1.z, b4 = b3 + q1.w;
    const float c1 = q2.x, c2 = c1 + q2.y, c3 = c2 + q2.z, c4 = c3 + q2.w;
    const float d1 = q3.x, d2 = d1 + q3.y, d3 = d2 + q3.z, d4 = d3 + q3.w;

    float s0 = a4, s1 = b4, s2 = c4, s3 = d4;
    #pragma unroll
    for (int off = 1; off < 32; off <<= 1) {
        float n0 = __shfl_up_sync(FULL, s0, off);
        float n1 = __shfl_up_sync(FULL, s1, off);
        float n2 = __shfl_up_sync(FULL, s2, off);
        float n3 = __shfl_up_sync(FULL, s3, off);
        if (lane >= off) { s0 += n0; s1 += n1; s2 += n2; s3 += n3; }
    }
    const float T0 = __shfl_sync(FULL, s0, 31);
    const float T1 = __shfl_sync(FULL, s1, 31);
    const float T2 = __shfl_sync(FULL, s2, 31);
    const float T3 = __shfl_sync(FULL, s3, 31);

    const float e0 = s0 - a4;
    const float e1 = T0 + (s1 - b4);
    const float e2 = T0 + T1 + (s2 - c4);
    const float e3 = T0 + T1 + T2 + (s3 - d4);
    const float total = T0 + T1 + T2 + T3;

    P4[lane]      = make_float4(e0 + a1, e0 + a2, e0 + a3, e0 + a4);
    P4[32 + lane] = make_float4(e1 + b1, e1 + b2, e1 + b3, e1 + b4);
    P4[64 + lane] = make_float4(e2 + c1, e2 + c2, e2 + c3, e2 + c4);
    P4[96 + lane] = make_float4(e3 + d1, e3 + d2, e3 + d3, e3 + d4);
    __syncwarp();

    #pragma unroll
    for (int c = 0; c < 4; ++c) {
        const int g = c * 32 + lane;
        float4 A;
        if (g < 124) {
            float4 Q1 = P4[g + 3];
            float4 Q2 = P4[g + 4];
            A = make_float4(Q1.w, Q2.x, Q2.y, Q2.z);
        } else {
            A = make_float4(total, total, total, total);
        }
        float4 B = (g >= 4) ? P4[g - 4] : make_float4(0.f, 0.f, 0.f, 0.f);
        __half2 h0 = __floats2half2_rn(A.x - B.x, A.y - B.y);
        __half2 h1 = __floats2half2_rn(A.z - B.z, A.w - B.w);
        uint2 u;
        u.x = *reinterpret_cast<unsigned*>(&h0);
        u.y = *reinterpret_cast<unsigned*>(&h1);
        cb2[g] = u;
    }
}

// 2-MUFU loss math: p via tanh.approx, softplus via log of the same tanh.
__device__ __forceinline__ void lane_math(float xv, float tv, float vsum,
                                          float& bce, float& ws, float& it, float& un) {
    const float w  = fmaf(5.0f, fabsf(vsum * KK_INV - tv), 1.0f);
    const float th = tanh_fast(0.5f * xv);
    const float p  = fmaf(0.5f, th, 0.5f);
    const float sp = fmaxf(xv, 0.0f) - __logf(fmaf(0.5f, fabsf(th), 0.5f));
    bce += sp - xv * tv;
    ws  += w;
    it  += p * tv * w;
    un  += (p + tv) * w;
}

// ---------------------------------------------------------------------------
// Software-pipelined fused kernel: grid (16, 32) = 512 blocks, block 128.
// Per iteration: prefetch tv/xv(g) -> produce group g+1 -> consume group g ->
// ONE barrier. Ring depth 44 makes all same-iteration slot accesses disjoint.
// ---------------------------------------------------------------------------
extern __shared__ char smem_raw[];

__global__ __launch_bounds__(NTHR, 4)
void fused_kernel(const float* __restrict__ pred,
                  const float* __restrict__ targ,
                  float* __restrict__ out) {
    __half* CB   = (__half*)smem_raw;                            // [NSLOT][W]
    float*  Pscr = (float*)(smem_raw + CB_BYTES);                // [4][W]
    float*  red  = (float*)(smem_raw + CB_BYTES + PSCR_BYTES);   // [4][NTHR]

    const int b    = blockIdx.y;
    const int tid  = threadIdx.x;
    const int w    = tid >> 5;
    const int lane = tid & 31;
    const int r0   = blockIdx.x * ROWS_PB;

    const float* __restrict__ tb = targ + (size_t)b * HW;
    const float* __restrict__ pb = pred + (size_t)b * HW;
    const float4* __restrict__ tb4 = (const float4*)tb;
    const float4* __restrict__ pb4 = (const float4*)pb;

    // Prologue: ring rows r0-15 .. r0+19 (35 rows, 4 warps, 9 rounds)
    #pragma unroll
    for (int k = 0; k < 9; ++k) {
        const int i = k * 4 + w;
        if (i < 35) {
            const int row = r0 - 15 + i;
            compute_hsum_row(tb, row, Pscr + w * W, CB + slotof(row) * W, lane);
        }
    }
    __syncthreads();

    // Initial vertical window (4 cols per thread)
    float vx = 0.f, vy = 0.f, vz = 0.f, vw = 0.f;
    #pragma unroll
    for (int i = 0; i < 31; ++i) {
        const int row = r0 - 15 + i;
        uint2 u = ((const uint2*)(CB + slotof(row) * W))[tid];
        float2 a = __half22float2(*reinterpret_cast<__half2*>(&u.x));
        float2 c = __half22float2(*reinterpret_cast<__half2*>(&u.y));
        vx += a.x; vy += a.y; vz += c.x; vw += c.y;
    }

    float bce_a = 0.f, wsum_a = 0.f, inter_a = 0.f, uni_a = 0.f;

    #pragma unroll
    for (int gr = 0; gr < ROWS_PB / 4; ++gr) {
        const int r = r0 + gr * 4;

        // Prefetch this group's tv/xv
        float4 TV[4], XV[4];
        #pragma unroll
        for (int j = 0; j < 4; ++j) {
            TV[j] = tb4[(r + j) * (W/4) + tid];
            XV[j] = pb4[(r + j) * (W/4) + tid];
        }

        // Produce NEXT group's ring rows (r+20 .. r+23), one per warp.
        // Slots recycled: rows r-24..-21 — disjoint from this group's reads.
        if (gr < ROWS_PB / 4 - 1) {
            const int row = r + 20 + w;
            compute_hsum_row(tb, row, Pscr + w * W, CB + slotof(row) * W, lane);
        }

        // Consume group gr (ring rows r-15 .. r+19, produced >= 1 barrier ago)
        #pragma unroll
        for (int j = 0; j < 4; ++j) {
            const int rr = r + j;
            lane_math(XV[j].x, TV[j].x, vx, bce_a, wsum_a, inter_a, uni_a);
            lane_math(XV[j].y, TV[j].y, vy, bce_a, wsum_a, inter_a, uni_a);
            lane_math(XV[j].z, TV[j].z, vz, bce_a, wsum_a, inter_a, uni_a);
            lane_math(XV[j].w, TV[j].w, vw, bce_a, wsum_a, inter_a, uni_a);

            uint2 ua = ((const uint2*)(CB + slotof(rr + 16) * W))[tid];
            uint2 us = ((const uint2*)(CB + slotof(rr - 15) * W))[tid];
            float2 aa = __half22float2(*reinterpret_cast<__half2*>(&ua.x));
            float2 ab = __half22float2(*reinterpret_cast<__half2*>(&ua.y));
            float2 sa = __half22float2(*reinterpret_cast<__half2*>(&us.x));
            float2 sb = __half22float2(*reinterpret_cast<__half2*>(&us.y));
            vx += aa.x - sa.x;
            vy += aa.y - sa.y;
            vz += ab.x - sb.x;
            vw += ab.y - sb.y;
        }
        __syncthreads();   // separates produce(g+1) writes from consume(g+1) reads
    }

    // Deterministic block reduction (fixed order)
    red[0 * NTHR + tid] = bce_a;
    red[1 * NTHR + tid] = wsum_a;
    red[2 * NTHR + tid] = inter_a;
    red[3 * NTHR + tid] = uni_a;
    __syncthreads();
    #pragma unroll
    for (int off = NTHR / 2; off > 0; off >>= 1) {
        if (tid < off) {
            red[0 * NTHR + tid] += red[0 * NTHR + tid + off];
            red[1 * NTHR + tid] += red[1 * NTHR + tid + off];
            red[2 * NTHR + tid] += red[2 * NTHR + tid + off];
            red[3 * NTHR + tid] += red[3 * NTHR + tid + off];
        }
        __syncthreads();
    }

    __shared__ unsigned last_flag;
    if (tid == 0) {
        const int blin = b * CHUNKS_PER_IMG + blockIdx.x;
        g_part[blin][0] = red[0 * NTHR];
        g_part[blin][1] = red[1 * NTHR];
        g_part[blin][2] = red[2 * NTHR];
        g_part[blin][3] = red[3 * NTHR];
        __threadfence();
        last_flag = (atomicAdd(&g_done, 1u) == NBLK - 1u);
    }
    __syncthreads();
    if (!last_flag) return;

    // ---- Last block: global finalize (fixed-order sums) ----
    __threadfence();
    if (tid == 0) g_done = 0;    // reset for next graph replay

    float acc = 0.0f;
    #pragma unroll
    for (int j = 0; j < NBLK / NTHR; ++j) acc += g_part[tid * (NBLK / NTHR) + j][0];
    red[tid] = acc;
    __syncthreads();
    #pragma unroll
    for (int off = NTHR / 2; off > 0; off >>= 1) {
        if (tid < off) red[tid] += red[tid + off];
        __syncthreads();
    }
    const float bce = red[0] * (1.0f / (float)NTOT);
    __syncthreads();

    if (tid < BATCH) {
        float ws = 0.0f, it = 0.0f, un = 0.0f;
        #pragma unroll
        for (int j = 0; j < CHUNKS_PER_IMG; ++j) {
            const int bl = tid * CHUNKS_PER_IMG + j;
            ws += g_part[bl][1];
            it += g_part[bl][2];
            un += g_part[bl][3];
        }
        const float w_bce = (ws * bce + 1e-8f) / (ws + 1e-8f);
        const float w_iou = 1.0f - (it + 1.0f + 1e-8f) / (un - it + 1.0f + 1e-8f);
        red[NTHR + tid] = w_bce + w_iou;
    }
    __syncthreads();
    if (tid == 0) {
        float a = 0.0f;
        #pragma unroll
        for (int i = 0; i < BATCH; ++i) a += red[NTHR + i];
        out[0] = a * (1.0f / (float)BATCH);
    }
}

// ---------------------------------------------------------------------------
extern "C" void kernel_launch(void* const* d_in, const int* in_sizes, int n_in,
                              void* d_out, int out_size) {
    const float* y_pred   = (const float*)d_in[0];
    const float* y_target = (const float*)d_in[1];
    float* out = (float*)d_out;

    cudaFuncSetAttribute(fused_kernel, cudaFuncAttributeMaxDynamicSharedMemorySize,
                         SMEM_TOTAL);

    dim3 g(NBLKY, BATCH);             // (16, 32) = 512 blocks
    fused_kernel<<<g, NTHR, SMEM_TOTAL>>>(y_pred, y_target, out);
}